// round 13
// baseline (speedup 1.0000x reference)
#include <cuda_runtime.h>
#include <cuda_fp16.h>
#include <cuda_bf16.h>

// SSIM fused single-kernel, tensor-core separable conv, register-resident
// intermediates (movmatrix), uniform sliding row-block pipeline over 64x64 tile.
// X,Y: [64,1,320,320] f32; window [1,1,7,7] rank-1 Gaussian. out = 1 - mean(ssim).
//
// Staging padded to 80 rows so the vertical pipeline is uniform:
//   out rows 16s..16s+15 = F0*H(16s) + F1*H(16s+16),  s = 0..3,
// with H tiles at m0 in {0,16,32,48,64}. Pad rows 70-79 only reach H(64) at
// F1 weights w[16+k-m] which are exactly 0 for k>5 -> finite pad is harmless.

typedef unsigned int u32;

#define IMG_H 320
#define IMG_W 320
#define N_IMG 64
#define TILE_W 64
#define TILE_H 64
#define IN_R 80              // 70 real rows + 10 pad rows
#define REAL_R 70
#define S_ST 72              // halfs per row = 144B = 9 x 16B (odd) -> ldmatrix conflict-free
#define GRID_X (IMG_W / TILE_W)   // 5
#define GRID_Y (IMG_H / TILE_H)   // 5
#define NBLOCKS (GRID_X * GRID_Y * N_IMG)   // 1600

#define C1_CONST 0.0004f
#define C2_CONST 0.0036f
#define COV_NORM_CONST (49.0f / 48.0f)

__device__ float g_part[NBLOCKS];
__device__ unsigned g_ticket;   // atomicInc wraps to 0 -> graph-replay safe

__device__ __forceinline__ u32 h2u(__half2 h) { return *reinterpret_cast<u32*>(&h); }
__device__ __forceinline__ __half2 u2h(u32 u) { return *reinterpret_cast<__half2*>(&u); }

__device__ __forceinline__ void ldsm_x4(u32 a, u32& r0, u32& r1, u32& r2, u32& r3) {
    asm volatile("ldmatrix.sync.aligned.m8n8.x4.shared.b16 {%0,%1,%2,%3}, [%4];"
                 : "=r"(r0), "=r"(r1), "=r"(r2), "=r"(r3) : "r"(a));
}
__device__ __forceinline__ void ldsm_x2t(u32 a, u32& r0, u32& r1) {
    asm volatile("ldmatrix.sync.aligned.m8n8.x2.trans.shared.b16 {%0,%1}, [%2];"
                 : "=r"(r0), "=r"(r1) : "r"(a));
}
__device__ __forceinline__ u32 movm_t(u32 a) {
    u32 d;
    asm volatile("movmatrix.sync.aligned.m8n8.trans.b16 %0, %1;" : "=r"(d) : "r"(a));
    return d;
}
__device__ __forceinline__ void mma_16816(float d[4], const u32 a[4], const u32 b[2],
                                          const float c[4]) {
    asm volatile("mma.sync.aligned.m16n8k16.row.col.f32.f16.f16.f32 "
                 "{%0,%1,%2,%3}, {%4,%5,%6,%7}, {%8,%9}, {%10,%11,%12,%13};"
                 : "=f"(d[0]), "=f"(d[1]), "=f"(d[2]), "=f"(d[3])
                 : "r"(a[0]), "r"(a[1]), "r"(a[2]), "r"(a[3]),
                   "r"(b[0]), "r"(b[1]),
                   "f"(c[0]), "f"(c[1]), "f"(c[2]), "f"(c[3]));
}

__global__ __launch_bounds__(256, 4)
void ssim_kernel(const float* __restrict__ X, const float* __restrict__ Y,
                 const float* __restrict__ W, float* __restrict__ out) {
    __shared__ __half sS[2][IN_R * S_ST];   // staging: x', y'  (22.5 KB)
    __shared__ __half F0m[256], F1m[256], T0m[128];
    __shared__ float warp_sums[8];
    __shared__ int is_last;

    const int tid  = threadIdx.x;
    const int lane = tid & 31;
    const int wid  = tid >> 5;
    const int bx = blockIdx.x * TILE_W;
    const int by = blockIdx.y * TILE_H;
    const int n  = blockIdx.z;

    // ---- Constant Toeplitz matrices from the rank-1 window ----
    const float wc = sqrtf(W[3 * 7 + 3]);
    {
        auto wv = [&](int d) -> __half {
            return (d >= 0 && d <= 6) ? __float2half(W[d * 7 + 3] / wc)
                                      : __float2half(0.0f);
        };
        int m = tid >> 4, k = tid & 15;
        F0m[tid] = wv(k - m);
        F1m[tid] = wv(16 + k - m);
        if (tid < 128) { int a = tid >> 3, b = tid & 7; T0m[tid] = wv(a - b - 1); }
    }

    const float* Xn = X + (size_t)n * IMG_H * IMG_W;
    const float* Yn = Y + (size_t)n * IMG_H * IMG_W;

    // ---- Phase 1: stage 70 real rows x 72 cols (orig cols bx-4 .. bx+67) ----
    for (int t = tid; t < REAL_R * 18; t += 256) {
        int r = t / 18, g = t - r * 18;
        int gy = by + r - 3;
        int c0 = bx - 4 + 4 * g;
        float4 xv = make_float4(0.f, 0.f, 0.f, 0.f);
        float4 yv = make_float4(0.f, 0.f, 0.f, 0.f);
        if ((unsigned)gy < (unsigned)IMG_H && (unsigned)c0 < (unsigned)IMG_W) {
            xv = *(const float4*)(Xn + gy * IMG_W + c0);
            yv = *(const float4*)(Yn + gy * IMG_W + c0);
        }
        __half2 x01 = __floats2half2_rn(xv.x - 0.5f, xv.y - 0.5f);
        __half2 x23 = __floats2half2_rn(xv.z - 0.5f, xv.w - 0.5f);
        __half2 y01 = __floats2half2_rn(yv.x - 0.5f, yv.y - 0.5f);
        __half2 y23 = __floats2half2_rn(yv.z - 0.5f, yv.w - 0.5f);
        int o = r * S_ST + 4 * g;
        *(uint2*)&sS[0][o] = make_uint2(h2u(x01), h2u(x23));
        *(uint2*)&sS[1][o] = make_uint2(h2u(y01), h2u(y23));
    }
    // pad rows 70..79: any finite value (weights are exactly zero there)
    for (int t = tid; t < (IN_R - REAL_R) * 18; t += 256) {
        int r = REAL_R + t / 18, g = t - (t / 18) * 18;
        int o = r * S_ST + 4 * g;
        uint2 padv = make_uint2(0xB800B800u, 0xB800B800u);   // -0.5 halves
        *(uint2*)&sS[0][o] = padv;
        *(uint2*)&sS[1][o] = padv;
    }
    __syncthreads();

    // ---- Constant fragments (per warp) ----
    const int arow = (lane & 7) + (((lane >> 3) & 1) << 3);   // 0..15
    const int acol = (lane & 16) >> 1;                        // 0 or 8
    u32 f0[4], f1[4], t0[2];
    ldsm_x4((u32)__cvta_generic_to_shared(&F0m[arow * 16 + acol]), f0[0], f0[1], f0[2], f0[3]);
    ldsm_x4((u32)__cvta_generic_to_shared(&F1m[arow * 16 + acol]), f1[0], f1[1], f1[2], f1[3]);
    ldsm_x2t((u32)__cvta_generic_to_shared(&T0m[(lane & 15) * 8]), t0[0], t0[1]);

    const int j = wid;   // n-block: output cols 8j..8j+7

    // per-warp staging base addresses (u32 shared addresses, computed once)
    const u32 baseX = (u32)__cvta_generic_to_shared(
        &sS[0][arow * S_ST + 8 * j + acol]);
    const u32 baseY = baseX + (u32)(IN_R * S_ST * sizeof(__half));

    // horizontal conv of rows m0..m0+15 -> B-fragment tile set (4 streams x 2)
    auto compute_h = [&](int m0, u32 tiles[4][2]) {
        const u32 off = (u32)(m0 * S_ST * sizeof(__half));
        u32 ax[4], ay[4], az[4], ap[4];
        ldsm_x4(baseX + off, ax[0], ax[1], ax[2], ax[3]);
        ldsm_x4(baseY + off, ay[0], ay[1], ay[2], ay[3]);
        #pragma unroll
        for (int q = 0; q < 4; q++) {
            __half2 xh = u2h(ax[q]), yh = u2h(ay[q]);
            az[q] = h2u(__hfma2(xh, xh, __hmul2(yh, yh)));
            ap[q] = h2u(__hmul2(xh, yh));
        }
        #pragma unroll
        for (int s = 0; s < 4; s++) {
            const u32* a = (s == 0) ? ax : (s == 1) ? ay : (s == 2) ? az : ap;
            float d[4] = {0.f, 0.f, 0.f, 0.f};
            mma_16816(d, a, t0, d);
            tiles[s][0] = movm_t(h2u(__floats2half2_rn(d[0], d[1])));
            tiles[s][1] = movm_t(h2u(__floats2half2_rn(d[2], d[3])));
        }
    };

    // ---- Uniform sliding pipeline, ping-pong tiles (no copies) ----
    float facc = 0.f;
    u32 tiles[2][4][2];
    compute_h(0, tiles[0]);
    #pragma unroll
    for (int step = 0; step < 4; step++) {
        u32 (*tcur)[2] = tiles[step & 1];
        u32 (*tnxt)[2] = tiles[(step + 1) & 1];
        compute_h(16 * (step + 1), tnxt);

        float Darr[4][4];
        #pragma unroll
        for (int s = 0; s < 4; s++) {
            float d[4] = {0.f, 0.f, 0.f, 0.f};
            mma_16816(d, f0, tcur[s], d);
            mma_16816(d, f1, tnxt[s], d);
            Darr[s][0] = d[0]; Darr[s][1] = d[1];
            Darr[s][2] = d[2]; Darr[s][3] = d[3];
        }
        #pragma unroll
        for (int e = 0; e < 4; e++) {
            float muxc = Darr[0][e], muyc = Darr[1][e];
            float s23c = Darr[2][e], spc  = Darr[3][e];
            float Pc   = fmaf(muxc, muxc, muyc * muyc);
            float ssum = (s23c - Pc)          * COV_NORM_CONST;
            float sxy  = (spc  - muxc * muyc) * COV_NORM_CONST;
            float mux = muxc + 0.5f;
            float muy = muyc + 0.5f;
            float muxy = mux * muy;
            float P    = fmaf(mux, mux, muy * muy);
            float num = fmaf(2.f, muxy, C1_CONST) * fmaf(2.f, sxy, C2_CONST);
            float den = (P + C1_CONST) * (ssum + C2_CONST);
            facc += __fdividef(num, den);
        }
    }

    // ---- Block reduction -> per-block float partial ----
    #pragma unroll
    for (int off = 16; off > 0; off >>= 1)
        facc += __shfl_down_sync(0xffffffffu, facc, off);
    if (lane == 0) warp_sums[wid] = facc;
    __syncthreads();
    if (tid == 0) {
        float bs = 0.f;
        #pragma unroll
        for (int w = 0; w < 8; w++) bs += warp_sums[w];
        int bid = blockIdx.x + GRID_X * (blockIdx.y + GRID_Y * blockIdx.z);
        g_part[bid] = bs;
        __threadfence();
        unsigned ticket = atomicInc(&g_ticket, NBLOCKS - 1);
        is_last = (ticket == NBLOCKS - 1);
    }
    __syncthreads();

    // ---- Last block: deterministic double reduction ----
    if (is_last) {
        __shared__ double dsums[8];
        double s = 0.0;
        for (int i = tid; i < NBLOCKS; i += 256) s += (double)__ldcg(&g_part[i]);
        #pragma unroll
        for (int off = 16; off > 0; off >>= 1)
            s += __shfl_down_sync(0xffffffffu, s, off);
        if (lane == 0) dsums[wid] = s;
        __syncthreads();
        if (tid == 0) {
            double t = 0.0;
            #pragma unroll
            for (int w = 0; w < 8; w++) t += dsums[w];
            double total = (double)N_IMG * IMG_H * IMG_W;
            out[0] = (float)(1.0 - t / total);
        }
    }
}

extern "C" void kernel_launch(void* const* d_in, const int* in_sizes, int n_in,
                              void* d_out, int out_size) {
    const float* X = (const float*)d_in[0];
    const float* Y = (const float*)d_in[1];
    const float* W = (const float*)d_in[2];
    float* out = (float*)d_out;

    dim3 grid(GRID_X, GRID_Y, N_IMG);
    ssim_kernel<<<grid, 256>>>(X, Y, W, out);
}

// round 14
// speedup vs baseline: 1.0508x; 1.0508x over previous
#include <cuda_runtime.h>
#include <cuda_fp16.h>
#include <cuda_bf16.h>

// SSIM fused single-kernel, tensor-core separable conv, register-resident
// intermediates (movmatrix), uniform sliding row-block pipeline over 64x64 tile,
// packed-f32x2 SSIM tail with cov-cancellation algebra.
// X,Y: [64,1,320,320] f32; window [1,1,7,7] rank-1 Gaussian. out = 1 - mean(ssim).
//
// Identity used in the tail (cov = 49/48 cancels between num and den):
//   ssim = [(2mc+t+K1)*(2sp-2mc+C2')] / [(Pc+t+K1)*(s23-Pc+C2')]
// where mc=muxc*muyc, Pc=muxc^2+muyc^2, t=muxc+muyc (centered stats),
// K1 = 0.5+C1, C2' = C2*48/49.

typedef unsigned int u32;
typedef unsigned long long u64;

#define IMG_H 320
#define IMG_W 320
#define N_IMG 64
#define TILE_W 64
#define TILE_H 64
#define IN_R 80              // 70 real rows + 10 pad rows
#define REAL_R 70
#define S_ST 72              // halfs per row = 144B = 9 x 16B (odd) -> ldmatrix conflict-free
#define GRID_X (IMG_W / TILE_W)   // 5
#define GRID_Y (IMG_H / TILE_H)   // 5
#define NBLOCKS (GRID_X * GRID_Y * N_IMG)   // 1600

#define C1_CONST 0.0004f
#define C2_CONST 0.0036f

__device__ float g_part[NBLOCKS];
__device__ unsigned g_ticket;   // atomicInc wraps to 0 -> graph-replay safe

__device__ __forceinline__ u32 h2u(__half2 h) { return *reinterpret_cast<u32*>(&h); }
__device__ __forceinline__ __half2 u2h(u32 u) { return *reinterpret_cast<__half2*>(&u); }

__device__ __forceinline__ u64 pack2(float lo, float hi) {
    u64 d; asm("mov.b64 %0, {%1,%2};" : "=l"(d) : "f"(lo), "f"(hi)); return d;
}
__device__ __forceinline__ void unpack2(u64 v, float& lo, float& hi) {
    asm("mov.b64 {%0,%1}, %2;" : "=f"(lo), "=f"(hi) : "l"(v));
}
__device__ __forceinline__ u64 fma2(u64 a, u64 b, u64 c) {
    u64 d; asm("fma.rn.f32x2 %0, %1, %2, %3;" : "=l"(d) : "l"(a), "l"(b), "l"(c)); return d;
}
__device__ __forceinline__ u64 mul2(u64 a, u64 b) {
    u64 d; asm("mul.rn.f32x2 %0, %1, %2;" : "=l"(d) : "l"(a), "l"(b)); return d;
}
__device__ __forceinline__ u64 add2(u64 a, u64 b) {
    u64 d; asm("add.rn.f32x2 %0, %1, %2;" : "=l"(d) : "l"(a), "l"(b)); return d;
}
__device__ __forceinline__ u64 sub2(u64 a, u64 b) {
    u64 d; asm("sub.rn.f32x2 %0, %1, %2;" : "=l"(d) : "l"(a), "l"(b)); return d;
}

__device__ __forceinline__ void ldsm_x4(u32 a, u32& r0, u32& r1, u32& r2, u32& r3) {
    asm volatile("ldmatrix.sync.aligned.m8n8.x4.shared.b16 {%0,%1,%2,%3}, [%4];"
                 : "=r"(r0), "=r"(r1), "=r"(r2), "=r"(r3) : "r"(a));
}
__device__ __forceinline__ void ldsm_x2t(u32 a, u32& r0, u32& r1) {
    asm volatile("ldmatrix.sync.aligned.m8n8.x2.trans.shared.b16 {%0,%1}, [%2];"
                 : "=r"(r0), "=r"(r1) : "r"(a));
}
__device__ __forceinline__ u32 movm_t(u32 a) {
    u32 d;
    asm volatile("movmatrix.sync.aligned.m8n8.trans.b16 %0, %1;" : "=r"(d) : "r"(a));
    return d;
}
__device__ __forceinline__ void mma_16816(float d[4], const u32 a[4], const u32 b[2],
                                          const float c[4]) {
    asm volatile("mma.sync.aligned.m16n8k16.row.col.f32.f16.f16.f32 "
                 "{%0,%1,%2,%3}, {%4,%5,%6,%7}, {%8,%9}, {%10,%11,%12,%13};"
                 : "=f"(d[0]), "=f"(d[1]), "=f"(d[2]), "=f"(d[3])
                 : "r"(a[0]), "r"(a[1]), "r"(a[2]), "r"(a[3]),
                   "r"(b[0]), "r"(b[1]),
                   "f"(c[0]), "f"(c[1]), "f"(c[2]), "f"(c[3]));
}

__global__ __launch_bounds__(256, 4)
void ssim_kernel(const float* __restrict__ X, const float* __restrict__ Y,
                 const float* __restrict__ W, float* __restrict__ out) {
    __shared__ __half sS[2][IN_R * S_ST];   // staging: x', y'  (22.5 KB)
    __shared__ __half F0m[256], F1m[256], T0m[128];
    __shared__ float warp_sums[8];
    __shared__ int is_last;

    const int tid  = threadIdx.x;
    const int lane = tid & 31;
    const int wid  = tid >> 5;
    const int bx = blockIdx.x * TILE_W;
    const int by = blockIdx.y * TILE_H;
    const int n  = blockIdx.z;

    // ---- Constant Toeplitz matrices from the rank-1 window ----
    const float wc = sqrtf(W[3 * 7 + 3]);
    {
        auto wv = [&](int d) -> __half {
            return (d >= 0 && d <= 6) ? __float2half(W[d * 7 + 3] / wc)
                                      : __float2half(0.0f);
        };
        int m = tid >> 4, k = tid & 15;
        F0m[tid] = wv(k - m);
        F1m[tid] = wv(16 + k - m);
        if (tid < 128) { int a = tid >> 3, b = tid & 7; T0m[tid] = wv(a - b - 1); }
    }

    const float* Xn = X + (size_t)n * IMG_H * IMG_W;
    const float* Yn = Y + (size_t)n * IMG_H * IMG_W;

    // ---- Phase 1: stage 70 real rows x 72 cols (orig cols bx-4 .. bx+67) ----
    for (int t = tid; t < REAL_R * 18; t += 256) {
        int r = t / 18, g = t - r * 18;
        int gy = by + r - 3;
        int c0 = bx - 4 + 4 * g;
        float4 xv = make_float4(0.f, 0.f, 0.f, 0.f);
        float4 yv = make_float4(0.f, 0.f, 0.f, 0.f);
        if ((unsigned)gy < (unsigned)IMG_H && (unsigned)c0 < (unsigned)IMG_W) {
            xv = *(const float4*)(Xn + gy * IMG_W + c0);
            yv = *(const float4*)(Yn + gy * IMG_W + c0);
        }
        __half2 x01 = __floats2half2_rn(xv.x - 0.5f, xv.y - 0.5f);
        __half2 x23 = __floats2half2_rn(xv.z - 0.5f, xv.w - 0.5f);
        __half2 y01 = __floats2half2_rn(yv.x - 0.5f, yv.y - 0.5f);
        __half2 y23 = __floats2half2_rn(yv.z - 0.5f, yv.w - 0.5f);
        int o = r * S_ST + 4 * g;
        *(uint2*)&sS[0][o] = make_uint2(h2u(x01), h2u(x23));
        *(uint2*)&sS[1][o] = make_uint2(h2u(y01), h2u(y23));
    }
    // pad rows 70..79: any finite value (weights are exactly zero there)
    for (int t = tid; t < (IN_R - REAL_R) * 18; t += 256) {
        int r = REAL_R + t / 18, g = t - (t / 18) * 18;
        int o = r * S_ST + 4 * g;
        uint2 padv = make_uint2(0xB800B800u, 0xB800B800u);   // -0.5 halves
        *(uint2*)&sS[0][o] = padv;
        *(uint2*)&sS[1][o] = padv;
    }
    __syncthreads();

    // ---- Constant fragments (per warp) ----
    const int arow = (lane & 7) + (((lane >> 3) & 1) << 3);   // 0..15
    const int acol = (lane & 16) >> 1;                        // 0 or 8
    u32 f0[4], f1[4], t0[2];
    ldsm_x4((u32)__cvta_generic_to_shared(&F0m[arow * 16 + acol]), f0[0], f0[1], f0[2], f0[3]);
    ldsm_x4((u32)__cvta_generic_to_shared(&F1m[arow * 16 + acol]), f1[0], f1[1], f1[2], f1[3]);
    ldsm_x2t((u32)__cvta_generic_to_shared(&T0m[(lane & 15) * 8]), t0[0], t0[1]);

    const int j = wid;   // n-block: output cols 8j..8j+7

    // per-warp staging base addresses (u32 shared addresses, computed once)
    const u32 baseX = (u32)__cvta_generic_to_shared(
        &sS[0][arow * S_ST + 8 * j + acol]);
    const u32 baseY = baseX + (u32)(IN_R * S_ST * sizeof(__half));

    // packed tail constants: K1 = 0.5 + C1 ; C2' = C2 * 48/49 (cov cancelled)
    const u64 K1p = pack2(0.5f + C1_CONST, 0.5f + C1_CONST);
    const float c2n = C2_CONST * (48.0f / 49.0f);
    const u64 C2p = pack2(c2n, c2n);

    // horizontal conv of rows m0..m0+15 -> B-fragment tile set (4 streams x 2)
    auto compute_h = [&](int m0, u32 tiles[4][2]) {
        const u32 off = (u32)(m0 * S_ST * sizeof(__half));
        u32 ax[4], ay[4], az[4], ap[4];
        ldsm_x4(baseX + off, ax[0], ax[1], ax[2], ax[3]);
        ldsm_x4(baseY + off, ay[0], ay[1], ay[2], ay[3]);
        #pragma unroll
        for (int q = 0; q < 4; q++) {
            __half2 xh = u2h(ax[q]), yh = u2h(ay[q]);
            az[q] = h2u(__hfma2(xh, xh, __hmul2(yh, yh)));
            ap[q] = h2u(__hmul2(xh, yh));
        }
        #pragma unroll
        for (int s = 0; s < 4; s++) {
            const u32* a = (s == 0) ? ax : (s == 1) ? ay : (s == 2) ? az : ap;
            float d[4] = {0.f, 0.f, 0.f, 0.f};
            mma_16816(d, a, t0, d);
            tiles[s][0] = movm_t(h2u(__floats2half2_rn(d[0], d[1])));
            tiles[s][1] = movm_t(h2u(__floats2half2_rn(d[2], d[3])));
        }
    };

    // ---- Uniform sliding pipeline, ping-pong tiles ----
    float facc = 0.f;
    u32 tiles[2][4][2];
    compute_h(0, tiles[0]);
    #pragma unroll
    for (int step = 0; step < 4; step++) {
        u32 (*tcur)[2] = tiles[step & 1];
        u32 (*tnxt)[2] = tiles[(step + 1) & 1];
        compute_h(16 * (step + 1), tnxt);

        float Darr[4][4];
        #pragma unroll
        for (int s = 0; s < 4; s++) {
            float d[4] = {0.f, 0.f, 0.f, 0.f};
            mma_16816(d, f0, tcur[s], d);
            mma_16816(d, f1, tnxt[s], d);
            Darr[s][0] = d[0]; Darr[s][1] = d[1];
            Darr[s][2] = d[2]; Darr[s][3] = d[3];
        }
        // packed-f32x2 SSIM on element pairs (0,1) and (2,3)
        #pragma unroll
        for (int p = 0; p < 2; p++) {
            u64 muxc = pack2(Darr[0][2 * p], Darr[0][2 * p + 1]);
            u64 muyc = pack2(Darr[1][2 * p], Darr[1][2 * p + 1]);
            u64 s23c = pack2(Darr[2][2 * p], Darr[2][2 * p + 1]);
            u64 spc  = pack2(Darr[3][2 * p], Darr[3][2 * p + 1]);
            u64 mc  = mul2(muxc, muyc);
            u64 Pc  = fma2(muxc, muxc, mul2(muyc, muyc));
            u64 tt  = add2(muxc, muyc);
            u64 mc2 = add2(mc, mc);
            u64 base = add2(tt, K1p);
            u64 numA = add2(mc2, base);                       // 2*muxy + C1
            u64 denA = add2(Pc, base);                        // P + C1
            u64 numB = add2(sub2(add2(spc, spc), mc2), C2p);  // (2sxy + C2)/cov
            u64 denB = add2(sub2(s23c, Pc), C2p);             // (ssum + C2)/cov
            u64 num = mul2(numA, numB);
            u64 den = mul2(denA, denB);
            float n0, n1, d0, d1;
            unpack2(num, n0, n1);
            unpack2(den, d0, d1);
            facc += __fdividef(n0, d0) + __fdividef(n1, d1);
        }
    }

    // ---- Block reduction -> per-block float partial ----
    #pragma unroll
    for (int off = 16; off > 0; off >>= 1)
        facc += __shfl_down_sync(0xffffffffu, facc, off);
    if (lane == 0) warp_sums[wid] = facc;
    __syncthreads();
    if (tid == 0) {
        float bs = 0.f;
        #pragma unroll
        for (int w = 0; w < 8; w++) bs += warp_sums[w];
        int bid = blockIdx.x + GRID_X * (blockIdx.y + GRID_Y * blockIdx.z);
        g_part[bid] = bs;
        __threadfence();
        unsigned ticket = atomicInc(&g_ticket, NBLOCKS - 1);
        is_last = (ticket == NBLOCKS - 1);
    }
    __syncthreads();

    // ---- Last block: deterministic double reduction ----
    if (is_last) {
        __shared__ double dsums[8];
        double s = 0.0;
        for (int i = tid; i < NBLOCKS; i += 256) s += (double)__ldcg(&g_part[i]);
        #pragma unroll
        for (int off = 16; off > 0; off >>= 1)
            s += __shfl_down_sync(0xffffffffu, s, off);
        if (lane == 0) dsums[wid] = s;
        __syncthreads();
        if (tid == 0) {
            double t = 0.0;
            #pragma unroll
            for (int w = 0; w < 8; w++) t += dsums[w];
            double total = (double)N_IMG * IMG_H * IMG_W;
            out[0] = (float)(1.0 - t / total);
        }
    }
}

extern "C" void kernel_launch(void* const* d_in, const int* in_sizes, int n_in,
                              void* d_out, int out_size) {
    const float* X = (const float*)d_in[0];
    const float* Y = (const float*)d_in[1];
    const float* W = (const float*)d_in[2];
    float* out = (float*)d_out;

    dim3 grid(GRID_X, GRID_Y, N_IMG);
    ssim_kernel<<<grid, 256>>>(X, Y, W, out);
}

// round 15
// speedup vs baseline: 1.1648x; 1.1085x over previous
#include <cuda_runtime.h>
#include <cuda_fp16.h>
#include <cuda_bf16.h>

// SSIM fused persistent-block kernel, tensor-core separable conv, register
// intermediates (movmatrix), double-buffered staging across tiles.
// X,Y: [64,1,320,320] f32; window [1,1,7,7] rank-1 Gaussian. out = 1 - mean(ssim).
//
// 1600 tiles (64x64), 608 persistent blocks; block b owns tiles b, b+608, b+1216.
// Per tile: stage next tile into the other buffer, compute current, one sync.
// Vertical pipeline uniform: out rows 16s..16s+15 = F0*H(16s)+F1*H(16s+16),
// H at m0 in {0,16,32,48,64}; staging padded to 80 rows (pad weights exactly 0).
// SSIM tail in packed f32x2 with cov-cancellation algebra.

typedef unsigned int u32;
typedef unsigned long long u64;

#define IMG_H 320
#define IMG_W 320
#define N_IMG 64
#define TILE_W 64
#define TILE_H 64
#define IN_R 80              // 70 real rows + 10 pad rows
#define REAL_R 70
#define S_ST 72              // halfs per row = 144B = 9 x 16B (odd) -> ldmatrix conflict-free
#define GRID_X 5
#define GRID_YT 5
#define TILES (GRID_X * GRID_YT * N_IMG)   // 1600
#define PBLOCKS 608                        // 4 x 152 SMs

#define C1_CONST 0.0004f
#define C2_CONST 0.0036f

__device__ float g_part[PBLOCKS];
__device__ unsigned g_ticket;   // atomicInc wraps to 0 -> graph-replay safe

__device__ __forceinline__ u32 h2u(__half2 h) { return *reinterpret_cast<u32*>(&h); }
__device__ __forceinline__ __half2 u2h(u32 u) { return *reinterpret_cast<__half2*>(&u); }

__device__ __forceinline__ u64 pack2(float lo, float hi) {
    u64 d; asm("mov.b64 %0, {%1,%2};" : "=l"(d) : "f"(lo), "f"(hi)); return d;
}
__device__ __forceinline__ void unpack2(u64 v, float& lo, float& hi) {
    asm("mov.b64 {%0,%1}, %2;" : "=f"(lo), "=f"(hi) : "l"(v));
}
__device__ __forceinline__ u64 fma2(u64 a, u64 b, u64 c) {
    u64 d; asm("fma.rn.f32x2 %0, %1, %2, %3;" : "=l"(d) : "l"(a), "l"(b), "l"(c)); return d;
}
__device__ __forceinline__ u64 mul2(u64 a, u64 b) {
    u64 d; asm("mul.rn.f32x2 %0, %1, %2;" : "=l"(d) : "l"(a), "l"(b)); return d;
}
__device__ __forceinline__ u64 add2(u64 a, u64 b) {
    u64 d; asm("add.rn.f32x2 %0, %1, %2;" : "=l"(d) : "l"(a), "l"(b)); return d;
}
__device__ __forceinline__ u64 sub2(u64 a, u64 b) {
    u64 d; asm("sub.rn.f32x2 %0, %1, %2;" : "=l"(d) : "l"(a), "l"(b)); return d;
}

__device__ __forceinline__ void ldsm_x4(u32 a, u32& r0, u32& r1, u32& r2, u32& r3) {
    asm volatile("ldmatrix.sync.aligned.m8n8.x4.shared.b16 {%0,%1,%2,%3}, [%4];"
                 : "=r"(r0), "=r"(r1), "=r"(r2), "=r"(r3) : "r"(a));
}
__device__ __forceinline__ void ldsm_x2t(u32 a, u32& r0, u32& r1) {
    asm volatile("ldmatrix.sync.aligned.m8n8.x2.trans.shared.b16 {%0,%1}, [%2];"
                 : "=r"(r0), "=r"(r1) : "r"(a));
}
__device__ __forceinline__ u32 movm_t(u32 a) {
    u32 d;
    asm volatile("movmatrix.sync.aligned.m8n8.trans.b16 %0, %1;" : "=r"(d) : "r"(a));
    return d;
}
__device__ __forceinline__ void mma_16816(float d[4], const u32 a[4], const u32 b[2],
                                          const float c[4]) {
    asm volatile("mma.sync.aligned.m16n8k16.row.col.f32.f16.f16.f32 "
                 "{%0,%1,%2,%3}, {%4,%5,%6,%7}, {%8,%9}, {%10,%11,%12,%13};"
                 : "=f"(d[0]), "=f"(d[1]), "=f"(d[2]), "=f"(d[3])
                 : "r"(a[0]), "r"(a[1]), "r"(a[2]), "r"(a[3]),
                   "r"(b[0]), "r"(b[1]),
                   "f"(c[0]), "f"(c[1]), "f"(c[2]), "f"(c[3]));
}

__global__ __launch_bounds__(256, 4)
void ssim_kernel(const float* __restrict__ X, const float* __restrict__ Y,
                 const float* __restrict__ W, float* __restrict__ out) {
    __shared__ __half sS[2][2][IN_R * S_ST];   // [buf][plane x'/y'][rows*cols] 45 KB
    __shared__ __half F0m[256], F1m[256], T0m[128];
    __shared__ float warp_sums[8];
    __shared__ int is_last;

    const int tid  = threadIdx.x;
    const int lane = tid & 31;
    const int wid  = tid >> 5;
    const int bid  = blockIdx.x;

    // ---- Constant Toeplitz matrices from the rank-1 window ----
    const float wc = sqrtf(W[3 * 7 + 3]);
    {
        auto wv = [&](int d) -> __half {
            return (d >= 0 && d <= 6) ? __float2half(W[d * 7 + 3] / wc)
                                      : __float2half(0.0f);
        };
        int m = tid >> 4, k = tid & 15;
        F0m[tid] = wv(k - m);
        F1m[tid] = wv(16 + k - m);
        if (tid < 128) { int a = tid >> 3, b = tid & 7; T0m[tid] = wv(a - b - 1); }
    }

    // ---- Pad rows 70..79 of BOTH buffers once (weights there are exactly 0) ----
    for (int t = tid; t < 2 * (IN_R - REAL_R) * 18; t += 256) {
        int buf = t / ((IN_R - REAL_R) * 18);
        int tt  = t - buf * (IN_R - REAL_R) * 18;
        int r = REAL_R + tt / 18, g = tt - (tt / 18) * 18;
        int o = r * S_ST + 4 * g;
        uint2 padv = make_uint2(0xB800B800u, 0xB800B800u);   // -0.5 halves
        *(uint2*)&sS[buf][0][o] = padv;
        *(uint2*)&sS[buf][1][o] = padv;
    }

    const __half2 negh = __floats2half2_rn(-0.5f, -0.5f);

    // stage tile 'tile' (70 real rows x 72 cols) into buffer 'buf'
    auto stage = [&](int tile, int buf) {
        int tx = tile % GRID_X;
        int rest = tile / GRID_X;
        int ty = rest % GRID_YT;
        int nn = rest / GRID_YT;
        int bxl = tx * TILE_W;
        int byl = ty * TILE_H;
        const float* Xn = X + (size_t)nn * (IMG_H * IMG_W);
        const float* Yn = Y + (size_t)nn * (IMG_H * IMG_W);
        for (int t = tid; t < REAL_R * 18; t += 256) {
            int r = t / 18, g = t - r * 18;
            int gy = byl + r - 3;
            int c0 = bxl - 4 + 4 * g;
            float4 xv = make_float4(0.f, 0.f, 0.f, 0.f);
            float4 yv = make_float4(0.f, 0.f, 0.f, 0.f);
            if ((unsigned)gy < (unsigned)IMG_H && (unsigned)c0 < (unsigned)IMG_W) {
                xv = *(const float4*)(Xn + gy * IMG_W + c0);
                yv = *(const float4*)(Yn + gy * IMG_W + c0);
            }
            // cvt packed, then exact fp16 centering with HADD2(-0.5)
            __half2 x01 = __hadd2(__floats2half2_rn(xv.x, xv.y), negh);
            __half2 x23 = __hadd2(__floats2half2_rn(xv.z, xv.w), negh);
            __half2 y01 = __hadd2(__floats2half2_rn(yv.x, yv.y), negh);
            __half2 y23 = __hadd2(__floats2half2_rn(yv.z, yv.w), negh);
            int o = r * S_ST + 4 * g;
            *(uint2*)&sS[buf][0][o] = make_uint2(h2u(x01), h2u(x23));
            *(uint2*)&sS[buf][1][o] = make_uint2(h2u(y01), h2u(y23));
        }
    };

    // ---- Constant fragments (per warp) ----
    const int arow = (lane & 7) + (((lane >> 3) & 1) << 3);   // 0..15
    const int acol = (lane & 16) >> 1;                        // 0 or 8
    __syncthreads();   // F0m/F1m/T0m + pad rows ready
    u32 f0[4], f1[4], t0[2];
    ldsm_x4((u32)__cvta_generic_to_shared(&F0m[arow * 16 + acol]), f0[0], f0[1], f0[2], f0[3]);
    ldsm_x4((u32)__cvta_generic_to_shared(&F1m[arow * 16 + acol]), f1[0], f1[1], f1[2], f1[3]);
    ldsm_x2t((u32)__cvta_generic_to_shared(&T0m[(lane & 15) * 8]), t0[0], t0[1]);

    const int j = wid;   // n-block: output cols 8j..8j+7
    const u32 fragoff = (u32)((arow * S_ST + 8 * j + acol) * sizeof(__half));
    const u32 planeoff = (u32)(IN_R * S_ST * sizeof(__half));

    // packed tail constants: K1 = 0.5 + C1 ; C2' = C2 * 48/49 (cov cancelled)
    const u64 K1p = pack2(0.5f + C1_CONST, 0.5f + C1_CONST);
    const float c2n = C2_CONST * (48.0f / 49.0f);
    const u64 C2p = pack2(c2n, c2n);

    float facc = 0.f;

    // ---- Persistent tile loop with double-buffered staging ----
    stage(bid, 0);
    __syncthreads();
    for (int tau = bid, k = 0; tau < TILES; tau += PBLOCKS, k ^= 1) {
        if (tau + PBLOCKS < TILES) stage(tau + PBLOCKS, k ^ 1);

        const u32 baseX = (u32)__cvta_generic_to_shared(&sS[k][0][0]) + fragoff;
        const u32 baseY = baseX + planeoff;

        // horizontal conv of rows m0..m0+15 -> B-fragment tile set (4 streams x 2)
        auto compute_h = [&](int m0, u32 tiles_[4][2]) {
            const u32 off = (u32)(m0 * S_ST * sizeof(__half));
            u32 ax[4], ay[4], az[4], ap[4];
            ldsm_x4(baseX + off, ax[0], ax[1], ax[2], ax[3]);
            ldsm_x4(baseY + off, ay[0], ay[1], ay[2], ay[3]);
            #pragma unroll
            for (int q = 0; q < 4; q++) {
                __half2 xh = u2h(ax[q]), yh = u2h(ay[q]);
                az[q] = h2u(__hfma2(xh, xh, __hmul2(yh, yh)));
                ap[q] = h2u(__hmul2(xh, yh));
            }
            #pragma unroll
            for (int s = 0; s < 4; s++) {
                const u32* a = (s == 0) ? ax : (s == 1) ? ay : (s == 2) ? az : ap;
                float d[4] = {0.f, 0.f, 0.f, 0.f};
                mma_16816(d, a, t0, d);
                tiles_[s][0] = movm_t(h2u(__floats2half2_rn(d[0], d[1])));
                tiles_[s][1] = movm_t(h2u(__floats2half2_rn(d[2], d[3])));
            }
        };

        u32 tiles[2][4][2];
        compute_h(0, tiles[0]);
        #pragma unroll
        for (int step = 0; step < 4; step++) {
            u32 (*tcur)[2] = tiles[step & 1];
            u32 (*tnxt)[2] = tiles[(step + 1) & 1];
            compute_h(16 * (step + 1), tnxt);

            float Darr[4][4];
            #pragma unroll
            for (int s = 0; s < 4; s++) {
                float d[4] = {0.f, 0.f, 0.f, 0.f};
                mma_16816(d, f0, tcur[s], d);
                mma_16816(d, f1, tnxt[s], d);
                Darr[s][0] = d[0]; Darr[s][1] = d[1];
                Darr[s][2] = d[2]; Darr[s][3] = d[3];
            }
            #pragma unroll
            for (int p = 0; p < 2; p++) {
                u64 muxc = pack2(Darr[0][2 * p], Darr[0][2 * p + 1]);
                u64 muyc = pack2(Darr[1][2 * p], Darr[1][2 * p + 1]);
                u64 s23c = pack2(Darr[2][2 * p], Darr[2][2 * p + 1]);
                u64 spc  = pack2(Darr[3][2 * p], Darr[3][2 * p + 1]);
                u64 mc  = mul2(muxc, muyc);
                u64 Pc  = fma2(muxc, muxc, mul2(muyc, muyc));
                u64 tt  = add2(muxc, muyc);
                u64 mc2 = add2(mc, mc);
                u64 base = add2(tt, K1p);
                u64 numA = add2(mc2, base);
                u64 denA = add2(Pc, base);
                u64 numB = add2(sub2(add2(spc, spc), mc2), C2p);
                u64 denB = add2(sub2(s23c, Pc), C2p);
                u64 num = mul2(numA, numB);
                u64 den = mul2(denA, denB);
                float n0, n1, d0, d1;
                unpack2(num, n0, n1);
                unpack2(den, d0, d1);
                facc += __fdividef(n0, d0) + __fdividef(n1, d1);
            }
        }
        __syncthreads();   // staged buffer ready / current buffer free for reuse
    }

    // ---- Block reduction (once per persistent block) ----
    #pragma unroll
    for (int off = 16; off > 0; off >>= 1)
        facc += __shfl_down_sync(0xffffffffu, facc, off);
    if (lane == 0) warp_sums[wid] = facc;
    __syncthreads();
    if (tid == 0) {
        float bs = 0.f;
        #pragma unroll
        for (int w = 0; w < 8; w++) bs += warp_sums[w];
        g_part[bid] = bs;
        __threadfence();
        unsigned ticket = atomicInc(&g_ticket, PBLOCKS - 1);
        is_last = (ticket == PBLOCKS - 1);
    }
    __syncthreads();

    // ---- Last block: deterministic double reduction ----
    if (is_last) {
        __shared__ double dsums[8];
        double s = 0.0;
        for (int i = tid; i < PBLOCKS; i += 256) s += (double)__ldcg(&g_part[i]);
        #pragma unroll
        for (int off = 16; off > 0; off >>= 1)
            s += __shfl_down_sync(0xffffffffu, s, off);
        if (lane == 0) dsums[wid] = s;
        __syncthreads();
        if (tid == 0) {
            double t = 0.0;
            #pragma unroll
            for (int w = 0; w < 8; w++) t += dsums[w];
            double total = (double)N_IMG * IMG_H * IMG_W;
            out[0] = (float)(1.0 - t / total);
        }
    }
}

extern "C" void kernel_launch(void* const* d_in, const int* in_sizes, int n_in,
                              void* d_out, int out_size) {
    const float* X = (const float*)d_in[0];
    const float* Y = (const float*)d_in[1];
    const float* W = (const float*)d_in[2];
    float* out = (float*)d_out;

    ssim_kernel<<<PBLOCKS, 256>>>(X, Y, W, out);
}

// round 16
// speedup vs baseline: 1.1794x; 1.0125x over previous
#include <cuda_runtime.h>
#include <cuda_fp16.h>
#include <cuda_bf16.h>

// SSIM fused persistent-block kernel, tensor-core separable conv, register
// intermediates (movmatrix), double-buffered staging, fraction-tree SSIM tail.
// X,Y: [64,1,320,320] f32; window [1,1,7,7] rank-1 Gaussian. out = 1 - mean(ssim).
//
// 1600 tiles (64x64), 608 persistent blocks; block b owns tiles b, b+608, b+1216.
// Vertical pipeline uniform: out rows 16s..16s+15 = F0*H(16s)+F1*H(16s+16),
// H at m0 in {0,16,32,48,64}; staging padded to 80 rows (pad weights exactly 0).
// Tail: 4 SSIM fractions per step combined into one division (exact algebra).

typedef unsigned int u32;
typedef unsigned long long u64;

#define IMG_H 320
#define IMG_W 320
#define N_IMG 64
#define TILE_W 64
#define TILE_H 64
#define IN_R 80              // 70 real rows + 10 pad rows
#define REAL_R 70
#define S_ST 72              // halfs per row = 144B = 9 x 16B (odd) -> ldmatrix conflict-free
#define GRID_X 5
#define GRID_YT 5
#define TILES (GRID_X * GRID_YT * N_IMG)   // 1600
#define PBLOCKS 608                        // 4 x 152 SMs

#define C1_CONST 0.0004f
#define C2_CONST 0.0036f

__device__ float g_part[PBLOCKS];
__device__ unsigned g_ticket;   // atomicInc wraps to 0 -> graph-replay safe

__device__ __forceinline__ u32 h2u(__half2 h) { return *reinterpret_cast<u32*>(&h); }
__device__ __forceinline__ __half2 u2h(u32 u) { return *reinterpret_cast<__half2*>(&u); }

__device__ __forceinline__ u64 pack2(float lo, float hi) {
    u64 d; asm("mov.b64 %0, {%1,%2};" : "=l"(d) : "f"(lo), "f"(hi)); return d;
}
__device__ __forceinline__ void unpack2(u64 v, float& lo, float& hi) {
    asm("mov.b64 {%0,%1}, %2;" : "=f"(lo), "=f"(hi) : "l"(v));
}
__device__ __forceinline__ u64 fma2(u64 a, u64 b, u64 c) {
    u64 d; asm("fma.rn.f32x2 %0, %1, %2, %3;" : "=l"(d) : "l"(a), "l"(b), "l"(c)); return d;
}
__device__ __forceinline__ u64 mul2(u64 a, u64 b) {
    u64 d; asm("mul.rn.f32x2 %0, %1, %2;" : "=l"(d) : "l"(a), "l"(b)); return d;
}
__device__ __forceinline__ u64 add2(u64 a, u64 b) {
    u64 d; asm("add.rn.f32x2 %0, %1, %2;" : "=l"(d) : "l"(a), "l"(b)); return d;
}
__device__ __forceinline__ u64 sub2(u64 a, u64 b) {
    u64 d; asm("sub.rn.f32x2 %0, %1, %2;" : "=l"(d) : "l"(a), "l"(b)); return d;
}

__device__ __forceinline__ void ldsm_x4(u32 a, u32& r0, u32& r1, u32& r2, u32& r3) {
    asm volatile("ldmatrix.sync.aligned.m8n8.x4.shared.b16 {%0,%1,%2,%3}, [%4];"
                 : "=r"(r0), "=r"(r1), "=r"(r2), "=r"(r3) : "r"(a));
}
__device__ __forceinline__ void ldsm_x2t(u32 a, u32& r0, u32& r1) {
    asm volatile("ldmatrix.sync.aligned.m8n8.x2.trans.shared.b16 {%0,%1}, [%2];"
                 : "=r"(r0), "=r"(r1) : "r"(a));
}
__device__ __forceinline__ u32 movm_t(u32 a) {
    u32 d;
    asm volatile("movmatrix.sync.aligned.m8n8.trans.b16 %0, %1;" : "=r"(d) : "r"(a));
    return d;
}
__device__ __forceinline__ void mma_16816(float d[4], const u32 a[4], const u32 b[2],
                                          const float c[4]) {
    asm volatile("mma.sync.aligned.m16n8k16.row.col.f32.f16.f16.f32 "
                 "{%0,%1,%2,%3}, {%4,%5,%6,%7}, {%8,%9}, {%10,%11,%12,%13};"
                 : "=f"(d[0]), "=f"(d[1]), "=f"(d[2]), "=f"(d[3])
                 : "r"(a[0]), "r"(a[1]), "r"(a[2]), "r"(a[3]),
                   "r"(b[0]), "r"(b[1]),
                   "f"(c[0]), "f"(c[1]), "f"(c[2]), "f"(c[3]));
}

__global__ __launch_bounds__(256, 4)
void ssim_kernel(const float* __restrict__ X, const float* __restrict__ Y,
                 const float* __restrict__ W, float* __restrict__ out) {
    __shared__ __half sS[2][2][IN_R * S_ST];   // [buf][plane x'/y'][rows*cols] 45 KB
    __shared__ __half F0m[256], F1m[256], T0m[128];
    __shared__ float warp_sums[8];
    __shared__ int is_last;

    const int tid  = threadIdx.x;
    const int lane = tid & 31;
    const int wid  = tid >> 5;
    const int bid  = blockIdx.x;

    // ---- Constant Toeplitz matrices from the rank-1 window ----
    const float wc = sqrtf(W[3 * 7 + 3]);
    {
        auto wv = [&](int d) -> __half {
            return (d >= 0 && d <= 6) ? __float2half(W[d * 7 + 3] / wc)
                                      : __float2half(0.0f);
        };
        int m = tid >> 4, k = tid & 15;
        F0m[tid] = wv(k - m);
        F1m[tid] = wv(16 + k - m);
        if (tid < 128) { int a = tid >> 3, b = tid & 7; T0m[tid] = wv(a - b - 1); }
    }

    // ---- Pad rows 70..79 of BOTH buffers once (weights there are exactly 0) ----
    for (int t = tid; t < 2 * (IN_R - REAL_R) * 9; t += 256) {
        int buf = t / ((IN_R - REAL_R) * 9);
        int tt  = t - buf * (IN_R - REAL_R) * 9;
        int r = REAL_R + tt / 9, g = tt - (tt / 9) * 9;
        int o = r * S_ST + 8 * g;
        uint4 padv = make_uint4(0xB800B800u, 0xB800B800u, 0xB800B800u, 0xB800B800u);
        *(uint4*)&sS[buf][0][o] = padv;
        *(uint4*)&sS[buf][1][o] = padv;
    }

    const __half2 negh = __floats2half2_rn(-0.5f, -0.5f);

    // stage tile 'tile' (70 real rows x 72 cols) into buffer 'buf'
    // tasks: 70 rows x 9 groups of 8 cols; STS.128 per plane per half-group.
    auto stage = [&](int tile, int buf) {
        int tx = tile % GRID_X;
        int rest = tile / GRID_X;
        int ty = rest % GRID_YT;
        int nn = rest / GRID_YT;
        int bxl = tx * TILE_W;
        int byl = ty * TILE_H;
        const float* Xn = X + (size_t)nn * (IMG_H * IMG_W);
        const float* Yn = Y + (size_t)nn * (IMG_H * IMG_W);
        const float4 z4 = make_float4(0.f, 0.f, 0.f, 0.f);
        for (int t = tid; t < REAL_R * 9; t += 256) {
            int r = t / 9, g = t - r * 9;
            int gy = byl + r - 3;
            int c0 = bxl - 4 + 8 * g;
            float4 xa = z4, xb = z4, ya = z4, yb = z4;
            if ((unsigned)gy < (unsigned)IMG_H) {
                const float* xrow = Xn + gy * IMG_W;
                const float* yrow = Yn + gy * IMG_W;
                if ((unsigned)c0 < (unsigned)IMG_W) {
                    xa = *(const float4*)(xrow + c0);
                    ya = *(const float4*)(yrow + c0);
                }
                if ((unsigned)(c0 + 4) < (unsigned)IMG_W) {
                    xb = *(const float4*)(xrow + c0 + 4);
                    yb = *(const float4*)(yrow + c0 + 4);
                }
            }
            uint4 vx, vy;
            vx.x = h2u(__hadd2(__floats2half2_rn(xa.x, xa.y), negh));
            vx.y = h2u(__hadd2(__floats2half2_rn(xa.z, xa.w), negh));
            vx.z = h2u(__hadd2(__floats2half2_rn(xb.x, xb.y), negh));
            vx.w = h2u(__hadd2(__floats2half2_rn(xb.z, xb.w), negh));
            vy.x = h2u(__hadd2(__floats2half2_rn(ya.x, ya.y), negh));
            vy.y = h2u(__hadd2(__floats2half2_rn(ya.z, ya.w), negh));
            vy.z = h2u(__hadd2(__floats2half2_rn(yb.x, yb.y), negh));
            vy.w = h2u(__hadd2(__floats2half2_rn(yb.z, yb.w), negh));
            int o = r * S_ST + 8 * g;
            *(uint4*)&sS[buf][0][o] = vx;
            *(uint4*)&sS[buf][1][o] = vy;
        }
    };

    // ---- Constant fragments (per warp) ----
    const int arow = (lane & 7) + (((lane >> 3) & 1) << 3);   // 0..15
    const int acol = (lane & 16) >> 1;                        // 0 or 8
    __syncthreads();   // F0m/F1m/T0m + pad rows ready
    u32 f0[4], f1[4], t0[2];
    ldsm_x4((u32)__cvta_generic_to_shared(&F0m[arow * 16 + acol]), f0[0], f0[1], f0[2], f0[3]);
    ldsm_x4((u32)__cvta_generic_to_shared(&F1m[arow * 16 + acol]), f1[0], f1[1], f1[2], f1[3]);
    ldsm_x2t((u32)__cvta_generic_to_shared(&T0m[(lane & 15) * 8]), t0[0], t0[1]);

    const int j = wid;   // n-block: output cols 8j..8j+7
    const u32 fragoff = (u32)((arow * S_ST + 8 * j + acol) * sizeof(__half));
    const u32 planeoff = (u32)(IN_R * S_ST * sizeof(__half));

    // packed tail constants: K1 = 0.5 + C1 ; C2' = C2 * 48/49 (cov cancelled)
    const u64 K1p = pack2(0.5f + C1_CONST, 0.5f + C1_CONST);
    const float c2n = C2_CONST * (48.0f / 49.0f);
    const u64 C2p = pack2(c2n, c2n);

    float facc = 0.f;

    // ---- Persistent tile loop with double-buffered staging ----
    stage(bid, 0);
    __syncthreads();
    for (int tau = bid, k = 0; tau < TILES; tau += PBLOCKS, k ^= 1) {
        if (tau + PBLOCKS < TILES) stage(tau + PBLOCKS, k ^ 1);

        const u32 baseX = (u32)__cvta_generic_to_shared(&sS[k][0][0]) + fragoff;
        const u32 baseY = baseX + planeoff;

        // horizontal conv of rows m0..m0+15 -> B-fragment tile set (4 streams x 2)
        auto compute_h = [&](int m0, u32 tiles_[4][2]) {
            const u32 off = (u32)(m0 * S_ST * sizeof(__half));
            u32 ax[4], ay[4], az[4], ap[4];
            ldsm_x4(baseX + off, ax[0], ax[1], ax[2], ax[3]);
            ldsm_x4(baseY + off, ay[0], ay[1], ay[2], ay[3]);
            #pragma unroll
            for (int q = 0; q < 4; q++) {
                __half2 xh = u2h(ax[q]), yh = u2h(ay[q]);
                az[q] = h2u(__hfma2(xh, xh, __hmul2(yh, yh)));
                ap[q] = h2u(__hmul2(xh, yh));
            }
            #pragma unroll
            for (int s = 0; s < 4; s++) {
                const u32* a = (s == 0) ? ax : (s == 1) ? ay : (s == 2) ? az : ap;
                float d[4] = {0.f, 0.f, 0.f, 0.f};
                mma_16816(d, a, t0, d);
                tiles_[s][0] = movm_t(h2u(__floats2half2_rn(d[0], d[1])));
                tiles_[s][1] = movm_t(h2u(__floats2half2_rn(d[2], d[3])));
            }
        };

        u32 tiles[2][4][2];
        compute_h(0, tiles[0]);
        #pragma unroll
        for (int step = 0; step < 4; step++) {
            u32 (*tcur)[2] = tiles[step & 1];
            u32 (*tnxt)[2] = tiles[(step + 1) & 1];
            compute_h(16 * (step + 1), tnxt);

            float Darr[4][4];
            #pragma unroll
            for (int s = 0; s < 4; s++) {
                float d[4] = {0.f, 0.f, 0.f, 0.f};
                mma_16816(d, f0, tcur[s], d);
                mma_16816(d, f1, tnxt[s], d);
                Darr[s][0] = d[0]; Darr[s][1] = d[1];
                Darr[s][2] = d[2]; Darr[s][3] = d[3];
            }
            // packed SSIM numerators/denominators, fraction-tree combine: 1 div/step
            float nsc[4], dsc[4];
            #pragma unroll
            for (int p = 0; p < 2; p++) {
                u64 muxc = pack2(Darr[0][2 * p], Darr[0][2 * p + 1]);
                u64 muyc = pack2(Darr[1][2 * p], Darr[1][2 * p + 1]);
                u64 s23c = pack2(Darr[2][2 * p], Darr[2][2 * p + 1]);
                u64 spc  = pack2(Darr[3][2 * p], Darr[3][2 * p + 1]);
                u64 mc  = mul2(muxc, muyc);
                u64 Pc  = fma2(muxc, muxc, mul2(muyc, muyc));
                u64 tt  = add2(muxc, muyc);
                u64 mc2 = add2(mc, mc);
                u64 base = add2(tt, K1p);
                u64 numA = add2(mc2, base);                       // 2*muxy + C1
                u64 denA = add2(Pc, base);                        // P + C1
                u64 numB = add2(sub2(add2(spc, spc), mc2), C2p);  // (2sxy + C2)/cov
                u64 denB = add2(sub2(s23c, Pc), C2p);             // (ssum + C2)/cov
                u64 num = mul2(numA, numB);
                u64 den = mul2(denA, denB);
                unpack2(num, nsc[2 * p], nsc[2 * p + 1]);
                unpack2(den, dsc[2 * p], dsc[2 * p + 1]);
            }
            float cr01 = fmaf(nsc[0], dsc[1], nsc[1] * dsc[0]);
            float dd01 = dsc[0] * dsc[1];
            float cr23 = fmaf(nsc[2], dsc[3], nsc[3] * dsc[2]);
            float dd23 = dsc[2] * dsc[3];
            float tnum = fmaf(cr01, dd23, cr23 * dd01);
            float tden = dd01 * dd23;
            facc += __fdividef(tnum, tden);
        }
        __syncthreads();   // staged buffer ready / current buffer free for reuse
    }

    // ---- Block reduction (once per persistent block) ----
    #pragma unroll
    for (int off = 16; off > 0; off >>= 1)
        facc += __shfl_down_sync(0xffffffffu, facc, off);
    if (lane == 0) warp_sums[wid] = facc;
    __syncthreads();
    if (tid == 0) {
        float bs = 0.f;
        #pragma unroll
        for (int w = 0; w < 8; w++) bs += warp_sums[w];
        g_part[bid] = bs;
        __threadfence();
        unsigned ticket = atomicInc(&g_ticket, PBLOCKS - 1);
        is_last = (ticket == PBLOCKS - 1);
    }
    __syncthreads();

    // ---- Last block: deterministic double reduction ----
    if (is_last) {
        __shared__ double dsums[8];
        double s = 0.0;
        for (int i = tid; i < PBLOCKS; i += 256) s += (double)__ldcg(&g_part[i]);
        #pragma unroll
        for (int off = 16; off > 0; off >>= 1)
            s += __shfl_down_sync(0xffffffffu, s, off);
        if (lane == 0) dsums[wid] = s;
        __syncthreads();
        if (tid == 0) {
            double t = 0.0;
            #pragma unroll
            for (int w = 0; w < 8; w++) t += dsums[w];
            double total = (double)N_IMG * IMG_H * IMG_W;
            out[0] = (float)(1.0 - t / total);
        }
    }
}

extern "C" void kernel_launch(void* const* d_in, const int* in_sizes, int n_in,
                              void* d_out, int out_size) {
    const float* X = (const float*)d_in[0];
    const float* Y = (const float*)d_in[1];
    const float* W = (const float*)d_in[2];
    float* out = (float*)d_out;

    ssim_kernel<<<PBLOCKS, 256>>>(X, Y, W, out);
}